// round 16
// baseline (speedup 1.0000x reference)
#include <cuda_runtime.h>
#include <cuda_fp16.h>
#include <cstdint>

#define EPSV 1e-5f
#define N4K  4096
#define BROWS 512

// ---------------- scratch (static __device__: allocation-free) ----------------
__device__ __half g_Mth[(size_t)N4K * N4K];   // injected matrix, TRANSPOSED [j][i], fp16
__device__ __half g_Ah[(size_t)BROWS * N4K];  // x rounded to fp16
__device__ float g_cw_part[32][N4K];          // partial col sumsq of weight (32 splits)
__device__ float g_cm_part[64][N4K];          // partial col sumsq of Mth
__device__ float g_invrn[BROWS];
__device__ float g_ql[N4K];

// ---------------- helpers ----------------
__device__ __forceinline__ uint32_t s2u(const void* p) {
    uint32_t a;
    asm("{ .reg .u64 t; cvta.to.shared.u64 t, %1; cvt.u32.u64 %0, t; }" : "=r"(a) : "l"(p));
    return a;
}
__device__ __forceinline__ void ldsm4(uint32_t& r0, uint32_t& r1, uint32_t& r2,
                                      uint32_t& r3, uint32_t addr) {
    asm volatile("ldmatrix.sync.aligned.m8n8.x4.shared.b16 {%0,%1,%2,%3}, [%4];"
                 : "=r"(r0), "=r"(r1), "=r"(r2), "=r"(r3) : "r"(addr));
}
// fp16-accumulate MMA: D(fp16x2 x2) = A*B + D
__device__ __forceinline__ void mma_f16acc(uint32_t& c0, uint32_t& c1,
                                           uint32_t a0, uint32_t a1, uint32_t a2, uint32_t a3,
                                           uint32_t b0, uint32_t b1) {
    asm volatile(
        "mma.sync.aligned.m16n8k16.row.col.f16.f16.f16.f16 "
        "{%0,%1}, {%2,%3,%4,%5}, {%6,%7}, {%0,%1};"
        : "+r"(c0), "+r"(c1)
        : "r"(a0), "r"(a1), "r"(a2), "r"(a3), "r"(b0), "r"(b1));
}
__device__ __forceinline__ void cpasync16(uint32_t dst, const void* src) {
    asm volatile("cp.async.cg.shared.global [%0], [%1], 16;" :: "r"(dst), "l"(src) : "memory");
}
#define SWZ(o) ((o) ^ (((o) >> 3) & 0x70))

// ---------------- K1: fused rownorm(x)+fp16  AND  colsq(w)+ql (32 splits) ----------------
__global__ void k_pre(const float* __restrict__ x, const float* __restrict__ w,
                      const int* __restrict__ qit, const int* __restrict__ iters) {
    int blk = blockIdx.x;
    if (blk < 64) {
        int wp = threadIdx.x >> 5, lid = threadIdx.x & 31;
        int b = blk * 8 + wp;
        const float4* p = (const float4*)(x + (size_t)b * N4K);
        __half* hrow = g_Ah + (size_t)b * N4K;
        float s = 0.f;
#pragma unroll
        for (int i = 0; i < 32; i++) {
            float4 v = p[lid + i * 32];
            s += v.x * v.x + v.y * v.y + v.z * v.z + v.w * v.w;
            __half2 h0 = __floats2half2_rn(v.x, v.y);
            __half2 h1 = __floats2half2_rn(v.z, v.w);
            uint2 u; u.x = *(uint32_t*)&h0; u.y = *(uint32_t*)&h1;
            *(uint2*)&hrow[(size_t)(lid + i * 32) * 4] = u;
        }
#pragma unroll
        for (int o = 16; o; o >>= 1) s += __shfl_xor_sync(0xFFFFFFFFu, s, o);
        if (lid == 0) g_invrn[b] = 1.0f / fmaxf(sqrtf(s), EPSV);
    } else {
        int jb = blk - 64;
        int j = (jb & 15) * 256 + threadIdx.x;
        int s = jb >> 4;                      // 32 splits of 128 rows
        if (s == 0) {
            int it = *iters + 1;
            bool active = (it - qit[j]) <= 200;
            g_ql[j] = ((it > 8000) && active) ? 0.15f : 0.0f;
        }
        const float* p = w + (size_t)(s * 128) * N4K + j;
        float acc = 0.f;
#pragma unroll 16
        for (int r = 0; r < 128; r++) { float v = p[(size_t)r * N4K]; acc += v * v; }
        g_cw_part[s][j] = acc;
    }
}

// ---------------- K2: build Mth[j][i] fp16 + column sumsq partials (vectorized) ----------------
__global__ __launch_bounds__(256) void k_build(const float* __restrict__ w,
                                               const float* __restrict__ qf) {
    __shared__ float swt[64][68];              // [j-local][i-local]
    __shared__ float sicw[64];
    int tid = threadIdx.x;
    int i0 = blockIdx.x * 64, j0 = blockIdx.y * 64;

    if (tid < 64) {
        float s = 0.f;
#pragma unroll
        for (int p = 0; p < 32; p++) s += g_cw_part[p][j0 + tid];
        sicw[tid] = 1.0f / fmaxf(sqrtf(s), EPSV);
    }
#pragma unroll
    for (int c = 0; c < 4; c++) {
        int chunk = tid + 256 * c;
        int il = chunk >> 4, jq = (chunk & 15) * 4;
        float4 v = *(const float4*)&w[(size_t)(i0 + il) * N4K + j0 + jq];
        swt[jq + 0][il] = v.x; swt[jq + 1][il] = v.y;
        swt[jq + 2][il] = v.z; swt[jq + 3][il] = v.w;
    }
    __syncthreads();

    int iq = (tid & 15) * 4;
    float4 q4 = *(const float4*)&g_ql[i0 + iq];
    float4 o4 = make_float4(1.f - q4.x, 1.f - q4.y, 1.f - q4.z, 1.f - q4.w);
    float part[4];
#pragma unroll
    for (int c = 0; c < 4; c++) {
        int jl = (tid >> 4) + 16 * c;
        int j = j0 + jl;
        float icw = sicw[jl];
        float4 wv = *(const float4*)&swt[jl][iq];
        float4 qv = *(const float4*)&qf[(size_t)j * N4K + i0 + iq];
        float m0 = wv.x * icw * o4.x + qv.x * q4.x;
        float m1 = wv.y * icw * o4.y + qv.y * q4.y;
        float m2 = wv.z * icw * o4.z + qv.z * q4.z;
        float m3 = wv.w * icw * o4.w + qv.w * q4.w;
        __half2 h0 = __floats2half2_rn(m0, m1);
        __half2 h1 = __floats2half2_rn(m2, m3);
        uint2 u; u.x = *(uint32_t*)&h0; u.y = *(uint32_t*)&h1;
        *(uint2*)&g_Mth[(size_t)j * N4K + i0 + iq] = u;
        float f0 = __low2float(h0), f1 = __high2float(h0);
        float f2 = __low2float(h1), f3 = __high2float(h1);
        part[c] = f0 * f0 + f1 * f1 + f2 * f2 + f3 * f3;
    }
#pragma unroll
    for (int c = 0; c < 4; c++) {
        float s = part[c];
        s += __shfl_xor_sync(0xFFFFFFFFu, s, 1);
        s += __shfl_xor_sync(0xFFFFFFFFu, s, 2);
        s += __shfl_xor_sync(0xFFFFFFFFu, s, 4);
        s += __shfl_xor_sync(0xFFFFFFFFu, s, 8);
        if ((tid & 15) == 0)
            g_cm_part[blockIdx.x][j0 + (tid >> 4) + 16 * c] = s;
    }
}

// ---------------- K3: fp16 mma.sync GEMM, 512 threads, fp16 accumulate ----------------
// BM=128, BN=128, BK=64; 16 warps (4m x 4n), warp tile 32x32, m16n8k16.
// fp16 accumulators chained over one k-tile (K=64), promoted to fp32 per tile.
// 4-stage cp.async pipeline, 32KB/stage.
static constexpr int SMEM_DYN = 1024 + 4 * 32768 + 512;
static constexpr int NKT = 64;                 // k-tiles of 64

__global__ __launch_bounds__(512, 1)
void k_gemm_mma(float* __restrict__ out) {
    extern __shared__ char smraw[];
    uint32_t raw = s2u(smraw);
    uint32_t sb = (raw + 1023) & ~1023u;       // 1024-aligned base
    char* smp = smraw + (sb - raw);
    float* sic = (float*)(smp + 4 * 32768);    // 128 floats: invcmn slice

    int tid = threadIdx.x;
    int lane = tid & 31, wid = tid >> 5;
    int wm = (wid >> 2) * 32;                  // warp m offset (0..96)
    int wn = (wid & 3) * 32;                   // warp n offset (0..96)
    int bn0 = blockIdx.x * 128, bm0 = blockIdx.y * 128;

    // ldmatrix per-lane addressing
    int q = lane >> 3, rr = lane & 7;
    uint32_t qk = (uint32_t)(q >> 1) * 16;     // +16B for high-k quads
    uint32_t xr = (uint32_t)(rr << 4);         // swizzle XOR
    int aRowL = wm + (q & 1) * 8 + rr;
    int bRowL = wn + (q & 1) * 8 + rr;

    float acc[2][4][4];
#pragma unroll
    for (int mt = 0; mt < 2; mt++)
#pragma unroll
        for (int n8 = 0; n8 < 4; n8++)
#pragma unroll
            for (int c = 0; c < 4; c++) acc[mt][n8][c] = 0.f;

#define LOADSTAGE(st, t)                                                          \
    {                                                                             \
        size_t k0 = (size_t)(t) * 64;                                             \
        uint32_t sa = sb + (uint32_t)(st) * 32768u;                               \
        _Pragma("unroll")                                                         \
        for (int i = 0; i < 2; i++) {                                             \
            int fid = tid + 512 * i;                                              \
            int r = fid >> 3, c = fid & 7;                                        \
            uint32_t so = SWZ((uint32_t)(r * 128 + c * 16));                      \
            cpasync16(sa + so, &g_Ah[(size_t)(bm0 + r) * N4K + k0 + c * 8]);      \
            cpasync16(sa + 16384u + so,                                           \
                      &g_Mth[(size_t)(bn0 + r) * N4K + k0 + c * 8]);              \
        }                                                                         \
    }
#define COMMIT() asm volatile("cp.async.commit_group;" ::: "memory")

    LOADSTAGE(0, 0); COMMIT();
    LOADSTAGE(1, 1); COMMIT();
    LOADSTAGE(2, 2); COMMIT();

    // ---- invcmn finalize for this CTA's 128 columns (overlaps with cp.async) ----
    {
        int c = tid >> 2, ph = tid & 3;
        float s = 0.f;
#pragma unroll
        for (int p = 0; p < 16; p++) s += g_cm_part[4 * p + ph][bn0 + c];
        s += __shfl_xor_sync(0xFFFFFFFFu, s, 1);
        s += __shfl_xor_sync(0xFFFFFFFFu, s, 2);
        if (ph == 0) sic[c] = 1.0f / fmaxf(sqrtf(s), EPSV);
    }

    for (int t = 0; t < NKT; t++) {
        asm volatile("cp.async.wait_group 2;" ::: "memory");
        __syncthreads();
        if (t + 3 < NKT) { LOADSTAGE((t + 3) & 3, t + 3); }
        COMMIT();

        uint32_t sa = sb + (uint32_t)(t & 3) * 32768u;
        uint32_t sB = sa + 16384u;

        // fp16 accumulators for this k-tile (K=64 chunk)
        uint32_t hc[2][4][2];
#pragma unroll
        for (int mt = 0; mt < 2; mt++)
#pragma unroll
            for (int n8 = 0; n8 < 4; n8++) { hc[mt][n8][0] = 0u; hc[mt][n8][1] = 0u; }

#pragma unroll
        for (int ks = 0; ks < 4; ks++) {
            uint32_t kb = ((uint32_t)(ks * 32) + qk) ^ xr;
            uint32_t a[2][4], b[2][4];
#pragma unroll
            for (int mt = 0; mt < 2; mt++)
                ldsm4(a[mt][0], a[mt][1], a[mt][2], a[mt][3],
                      sa + (uint32_t)(aRowL + mt * 16) * 128 + kb);
#pragma unroll
            for (int nt = 0; nt < 2; nt++)
                ldsm4(b[nt][0], b[nt][1], b[nt][2], b[nt][3],
                      sB + (uint32_t)(bRowL + nt * 16) * 128 + kb);
#pragma unroll
            for (int mt = 0; mt < 2; mt++)
#pragma unroll
                for (int n8 = 0; n8 < 4; n8++)
                    mma_f16acc(hc[mt][n8][0], hc[mt][n8][1],
                               a[mt][0], a[mt][1], a[mt][2], a[mt][3],
                               b[n8 >> 1][n8 & 1], b[n8 >> 1][(n8 & 1) + 2]);
        }

        // promote fp16 chunk sums into fp32 accumulators
#pragma unroll
        for (int mt = 0; mt < 2; mt++)
#pragma unroll
            for (int n8 = 0; n8 < 4; n8++) {
                float2 f0 = __half22float2(*(__half2*)&hc[mt][n8][0]);
                float2 f1 = __half22float2(*(__half2*)&hc[mt][n8][1]);
                acc[mt][n8][0] += f0.x; acc[mt][n8][1] += f0.y;
                acc[mt][n8][2] += f1.x; acc[mt][n8][3] += f1.y;
            }
    }

    // ---- epilogue: fold row + column norms, write fp32 ----
    int g4 = lane >> 2, t4 = lane & 3;
#pragma unroll
    for (int mt = 0; mt < 2; mt++) {
        int row0 = bm0 + wm + mt * 16 + g4;
        int row1 = row0 + 8;
        float ir0 = g_invrn[row0], ir1 = g_invrn[row1];
#pragma unroll
        for (int n8 = 0; n8 < 4; n8++) {
            int cl = wn + n8 * 8 + 2 * t4;
            int col = bn0 + cl;
            float c0 = sic[cl], c1 = sic[cl + 1];
            float2 v0 = make_float2(acc[mt][n8][0] * ir0 * c0, acc[mt][n8][1] * ir0 * c1);
            float2 v1 = make_float2(acc[mt][n8][2] * ir1 * c0, acc[mt][n8][3] * ir1 * c1);
            *(float2*)&out[(size_t)row0 * N4K + col] = v0;
            *(float2*)&out[(size_t)row1 * N4K + col] = v1;
        }
    }
}

// ---------------- launch ----------------
extern "C" void kernel_launch(void* const* d_in, const int* in_sizes, int n_in,
                              void* d_out, int out_size) {
    const float* x   = (const float*)d_in[0];   // (512, 4096)
    const float* w   = (const float*)d_in[1];   // (4096, 4096)
    const float* qf  = (const float*)d_in[2];   // (4096, 4096)
    const int*   qit = (const int*)d_in[3];     // (4096,)
    const int*   it  = (const int*)d_in[4];     // scalar
    float* out = (float*)d_out;                 // (512, 4096) fp32

    cudaFuncSetAttribute(k_gemm_mma, cudaFuncAttributeMaxDynamicSharedMemorySize, SMEM_DYN);

    k_pre<<<576, 256>>>(x, w, qit, it);
    k_build<<<dim3(64, 64), 256>>>(w, qf);
    k_gemm_mma<<<dim3(32, 4), 512, SMEM_DYN>>>(out);
}

// round 17
// speedup vs baseline: 1.0302x; 1.0302x over previous
#include <cuda_runtime.h>
#include <cuda_fp16.h>
#include <cstdint>

#define EPSV 1e-5f
#define N4K  4096
#define BROWS 512

// ---------------- scratch (static __device__: allocation-free) ----------------
__device__ __half g_Mth[(size_t)N4K * N4K];   // injected matrix, TRANSPOSED [j][i], fp16
__device__ __half g_Ah[(size_t)BROWS * N4K];  // x rounded to fp16
__device__ float g_cw_part[64][N4K];          // partial col sumsq of weight (64 splits)
__device__ float g_cm_part[64][N4K];          // partial col sumsq of Mth
__device__ float g_invrn[BROWS];
__device__ float g_ql[N4K];

// ---------------- helpers ----------------
__device__ __forceinline__ uint32_t s2u(const void* p) {
    uint32_t a;
    asm("{ .reg .u64 t; cvta.to.shared.u64 t, %1; cvt.u32.u64 %0, t; }" : "=r"(a) : "l"(p));
    return a;
}
__device__ __forceinline__ void ldsm4(uint32_t& r0, uint32_t& r1, uint32_t& r2,
                                      uint32_t& r3, uint32_t addr) {
    asm volatile("ldmatrix.sync.aligned.m8n8.x4.shared.b16 {%0,%1,%2,%3}, [%4];"
                 : "=r"(r0), "=r"(r1), "=r"(r2), "=r"(r3) : "r"(addr));
}
__device__ __forceinline__ void mma_f16(float& d0, float& d1, float& d2, float& d3,
                                        uint32_t a0, uint32_t a1, uint32_t a2, uint32_t a3,
                                        uint32_t b0, uint32_t b1) {
    asm volatile(
        "mma.sync.aligned.m16n8k16.row.col.f32.f16.f16.f32 "
        "{%0,%1,%2,%3}, {%4,%5,%6,%7}, {%8,%9}, {%0,%1,%2,%3};"
        : "+f"(d0), "+f"(d1), "+f"(d2), "+f"(d3)
        : "r"(a0), "r"(a1), "r"(a2), "r"(a3), "r"(b0), "r"(b1));
}
__device__ __forceinline__ void cpasync16(uint32_t dst, const void* src) {
    asm volatile("cp.async.cg.shared.global [%0], [%1], 16;" :: "r"(dst), "l"(src) : "memory");
}
#define SWZ(o) ((o) ^ (((o) >> 3) & 0x70))

// ---------------- K1: fused rownorm(x)+fp16  AND  colsq(w)+ql (64 splits) ----------------
__global__ void k_pre(const float* __restrict__ x, const float* __restrict__ w,
                      const int* __restrict__ qit, const int* __restrict__ iters) {
    int blk = blockIdx.x;
    if (blk < 64) {
        int wp = threadIdx.x >> 5, lid = threadIdx.x & 31;
        int b = blk * 8 + wp;
        const float4* p = (const float4*)(x + (size_t)b * N4K);
        __half* hrow = g_Ah + (size_t)b * N4K;
        float s = 0.f;
#pragma unroll
        for (int i = 0; i < 32; i++) {
            float4 v = p[lid + i * 32];
            s += v.x * v.x + v.y * v.y + v.z * v.z + v.w * v.w;
            __half2 h0 = __floats2half2_rn(v.x, v.y);
            __half2 h1 = __floats2half2_rn(v.z, v.w);
            uint2 u; u.x = *(uint32_t*)&h0; u.y = *(uint32_t*)&h1;
            *(uint2*)&hrow[(size_t)(lid + i * 32) * 4] = u;
        }
#pragma unroll
        for (int o = 16; o; o >>= 1) s += __shfl_xor_sync(0xFFFFFFFFu, s, o);
        if (lid == 0) g_invrn[b] = 1.0f / fmaxf(sqrtf(s), EPSV);
    } else {
        int jb = blk - 64;
        int j = (jb & 15) * 256 + threadIdx.x;
        int s = jb >> 4;                      // 64 splits of 64 rows
        if (s == 0) {
            int it = *iters + 1;
            bool active = (it - qit[j]) <= 200;
            g_ql[j] = ((it > 8000) && active) ? 0.15f : 0.0f;
        }
        const float* p = w + (size_t)(s * 64) * N4K + j;
        float acc = 0.f;
#pragma unroll 16
        for (int r = 0; r < 64; r++) { float v = p[(size_t)r * N4K]; acc += v * v; }
        g_cw_part[s][j] = acc;
    }
}

// ---------------- K2: build Mth[j][i] fp16 + column sumsq partials (vectorized) ----------------
__global__ __launch_bounds__(256) void k_build(const float* __restrict__ w,
                                               const float* __restrict__ qf) {
    __shared__ float swt[64][68];              // [j-local][i-local]
    __shared__ float sicw[64];
    int tid = threadIdx.x;
    int i0 = blockIdx.x * 64, j0 = blockIdx.y * 64;

    if (tid < 64) {
        float s = 0.f;
#pragma unroll
        for (int p = 0; p < 64; p++) s += g_cw_part[p][j0 + tid];
        sicw[tid] = 1.0f / fmaxf(sqrtf(s), EPSV);
    }
#pragma unroll
    for (int c = 0; c < 4; c++) {
        int chunk = tid + 256 * c;
        int il = chunk >> 4, jq = (chunk & 15) * 4;
        float4 v = *(const float4*)&w[(size_t)(i0 + il) * N4K + j0 + jq];
        swt[jq + 0][il] = v.x; swt[jq + 1][il] = v.y;
        swt[jq + 2][il] = v.z; swt[jq + 3][il] = v.w;
    }
    __syncthreads();

    int iq = (tid & 15) * 4;
    float4 q4 = *(const float4*)&g_ql[i0 + iq];
    float4 o4 = make_float4(1.f - q4.x, 1.f - q4.y, 1.f - q4.z, 1.f - q4.w);
    float part[4];
#pragma unroll
    for (int c = 0; c < 4; c++) {
        int jl = (tid >> 4) + 16 * c;
        int j = j0 + jl;
        float icw = sicw[jl];
        float4 wv = *(const float4*)&swt[jl][iq];
        float4 qv = *(const float4*)&qf[(size_t)j * N4K + i0 + iq];
        float m0 = wv.x * icw * o4.x + qv.x * q4.x;
        float m1 = wv.y * icw * o4.y + qv.y * q4.y;
        float m2 = wv.z * icw * o4.z + qv.z * q4.z;
        float m3 = wv.w * icw * o4.w + qv.w * q4.w;
        __half2 h0 = __floats2half2_rn(m0, m1);
        __half2 h1 = __floats2half2_rn(m2, m3);
        uint2 u; u.x = *(uint32_t*)&h0; u.y = *(uint32_t*)&h1;
        *(uint2*)&g_Mth[(size_t)j * N4K + i0 + iq] = u;
        float f0 = __low2float(h0), f1 = __high2float(h0);
        float f2 = __low2float(h1), f3 = __high2float(h1);
        part[c] = f0 * f0 + f1 * f1 + f2 * f2 + f3 * f3;
    }
#pragma unroll
    for (int c = 0; c < 4; c++) {
        float s = part[c];
        s += __shfl_xor_sync(0xFFFFFFFFu, s, 1);
        s += __shfl_xor_sync(0xFFFFFFFFu, s, 2);
        s += __shfl_xor_sync(0xFFFFFFFFu, s, 4);
        s += __shfl_xor_sync(0xFFFFFFFFu, s, 8);
        if ((tid & 15) == 0)
            g_cm_part[blockIdx.x][j0 + (tid >> 4) + 16 * c] = s;
    }
}

// ---------------- K3: fp16 mma.sync GEMM, 512 threads (+ inline invcmn) ----------------
// BM=128, BN=128, BK=64; 16 warps (4m x 4n), warp tile 32x32, m16n8k16.
// 4-stage cp.async pipeline, 32KB/stage. (R9/R15 config)
static constexpr int SMEM_DYN = 1024 + 4 * 32768 + 512;
static constexpr int NKT = 64;                 // k-tiles of 64

__global__ __launch_bounds__(512, 1)
void k_gemm_mma(float* __restrict__ out) {
    extern __shared__ char smraw[];
    uint32_t raw = s2u(smraw);
    uint32_t sb = (raw + 1023) & ~1023u;       // 1024-aligned base
    char* smp = smraw + (sb - raw);
    float* sic = (float*)(smp + 4 * 32768);    // 128 floats: invcmn slice

    int tid = threadIdx.x;
    int lane = tid & 31, wid = tid >> 5;
    int wm = (wid >> 2) * 32;                  // warp m offset (0..96)
    int wn = (wid & 3) * 32;                   // warp n offset (0..96)
    int bn0 = blockIdx.x * 128, bm0 = blockIdx.y * 128;

    // ldmatrix per-lane addressing
    int q = lane >> 3, rr = lane & 7;
    uint32_t qk = (uint32_t)(q >> 1) * 16;     // +16B for high-k quads
    uint32_t xr = (uint32_t)(rr << 4);         // swizzle XOR
    int aRowL = wm + (q & 1) * 8 + rr;
    int bRowL = wn + (q & 1) * 8 + rr;

    float acc[2][4][4];
#pragma unroll
    for (int mt = 0; mt < 2; mt++)
#pragma unroll
        for (int n8 = 0; n8 < 4; n8++)
#pragma unroll
            for (int c = 0; c < 4; c++) acc[mt][n8][c] = 0.f;

#define LOADSTAGE(st, t)                                                          \
    {                                                                             \
        size_t k0 = (size_t)(t) * 64;                                             \
        uint32_t sa = sb + (uint32_t)(st) * 32768u;                               \
        _Pragma("unroll")                                                         \
        for (int i = 0; i < 2; i++) {                                             \
            int fid = tid + 512 * i;                                              \
            int r = fid >> 3, c = fid & 7;                                        \
            uint32_t so = SWZ((uint32_t)(r * 128 + c * 16));                      \
            cpasync16(sa + so, &g_Ah[(size_t)(bm0 + r) * N4K + k0 + c * 8]);      \
            cpasync16(sa + 16384u + so,                                           \
                      &g_Mth[(size_t)(bn0 + r) * N4K + k0 + c * 8]);              \
        }                                                                         \
    }
#define COMMIT() asm volatile("cp.async.commit_group;" ::: "memory")

    LOADSTAGE(0, 0); COMMIT();
    LOADSTAGE(1, 1); COMMIT();
    LOADSTAGE(2, 2); COMMIT();

    // ---- invcmn finalize for this CTA's 128 columns (overlaps with cp.async) ----
    {
        int c = tid >> 2, ph = tid & 3;
        float s = 0.f;
#pragma unroll
        for (int p = 0; p < 16; p++) s += g_cm_part[4 * p + ph][bn0 + c];
        s += __shfl_xor_sync(0xFFFFFFFFu, s, 1);
        s += __shfl_xor_sync(0xFFFFFFFFu, s, 2);
        if (ph == 0) sic[c] = 1.0f / fmaxf(sqrtf(s), EPSV);
    }

    for (int t = 0; t < NKT; t++) {
        asm volatile("cp.async.wait_group 2;" ::: "memory");
        __syncthreads();
        if (t + 3 < NKT) { LOADSTAGE((t + 3) & 3, t + 3); }
        COMMIT();

        uint32_t sa = sb + (uint32_t)(t & 3) * 32768u;
        uint32_t sB = sa + 16384u;
#pragma unroll
        for (int ks = 0; ks < 4; ks++) {
            uint32_t kb = ((uint32_t)(ks * 32) + qk) ^ xr;
            uint32_t a[2][4], b[2][4];
#pragma unroll
            for (int mt = 0; mt < 2; mt++)
                ldsm4(a[mt][0], a[mt][1], a[mt][2], a[mt][3],
                      sa + (uint32_t)(aRowL + mt * 16) * 128 + kb);
#pragma unroll
            for (int nt = 0; nt < 2; nt++)
                ldsm4(b[nt][0], b[nt][1], b[nt][2], b[nt][3],
                      sB + (uint32_t)(bRowL + nt * 16) * 128 + kb);
#pragma unroll
            for (int mt = 0; mt < 2; mt++)
#pragma unroll
                for (int n8 = 0; n8 < 4; n8++)
                    mma_f16(acc[mt][n8][0], acc[mt][n8][1], acc[mt][n8][2], acc[mt][n8][3],
                            a[mt][0], a[mt][1], a[mt][2], a[mt][3],
                            b[n8 >> 1][n8 & 1], b[n8 >> 1][(n8 & 1) + 2]);
        }
    }

    // ---- epilogue: fold row + column norms, write fp32 ----
    int g4 = lane >> 2, t4 = lane & 3;
#pragma unroll
    for (int mt = 0; mt < 2; mt++) {
        int row0 = bm0 + wm + mt * 16 + g4;
        int row1 = row0 + 8;
        float ir0 = g_invrn[row0], ir1 = g_invrn[row1];
#pragma unroll
        for (int n8 = 0; n8 < 4; n8++) {
            int cl = wn + n8 * 8 + 2 * t4;
            int col = bn0 + cl;
            float c0 = sic[cl], c1 = sic[cl + 1];
            float2 v0 = make_float2(acc[mt][n8][0] * ir0 * c0, acc[mt][n8][1] * ir0 * c1);
            float2 v1 = make_float2(acc[mt][n8][2] * ir1 * c0, acc[mt][n8][3] * ir1 * c1);
            *(float2*)&out[(size_t)row0 * N4K + col] = v0;
            *(float2*)&out[(size_t)row1 * N4K + col] = v1;
        }
    }
}

// ---------------- launch ----------------
extern "C" void kernel_launch(void* const* d_in, const int* in_sizes, int n_in,
                              void* d_out, int out_size) {
    const float* x   = (const float*)d_in[0];   // (512, 4096)
    const float* w   = (const float*)d_in[1];   // (4096, 4096)
    const float* qf  = (const float*)d_in[2];   // (4096, 4096)
    const int*   qit = (const int*)d_in[3];     // (4096,)
    const int*   it  = (const int*)d_in[4];     // scalar
    float* out = (float*)d_out;                 // (512, 4096) fp32

    cudaFuncSetAttribute(k_gemm_mma, cudaFuncAttributeMaxDynamicSharedMemorySize, SMEM_DYN);

    k_pre<<<1088, 256>>>(x, w, qit, it);
    k_build<<<dim3(64, 64), 256>>>(w, qf);
    k_gemm_mma<<<dim3(32, 4), 512, SMEM_DYN>>>(out);
}